// round 9
// baseline (speedup 1.0000x reference)
#include <cuda_runtime.h>
#include <cuda_bf16.h>
#include <cuda_fp16.h>
#include <cstdint>

#define NNODE 4096
#define CDIM  768
#define HDIM  512
#define ODIM  50
#define OPAD  64

#define EPI_SIM  0
#define EPI_XW1T 1
#define EPI_H    2
#define EPI_HW2T 3
#define EPI_G    4

#define CAND_CAP 65536
#define FIXWIN 0.12f

// ---------------- device scratch (static: no allocations allowed) -------------
// Node-indexed arrays live in SORTED space (label-0 first, stable within label).
// g_perm: sorted -> original. g_iperm: original -> sorted.
__device__ __align__(16) __nv_bfloat16 g_a01[(size_t)NNODE * NNODE];
__device__ __align__(16) __half        g_xf16[(size_t)NNODE * CDIM];
__device__ __align__(16) __nv_bfloat16 g_xbh[(size_t)NNODE * CDIM];
__device__ __align__(16) __nv_bfloat16 g_w1th[(size_t)HDIM * CDIM];
__device__ __align__(16) __nv_bfloat16 g_w2th[(size_t)OPAD * HDIM];
__device__ __align__(16) __nv_bfloat16 g_xw1th[(size_t)HDIM * NNODE];
__device__ __align__(16) __nv_bfloat16 g_hh[(size_t)NNODE * HDIM];
__device__ __align__(16) __nv_bfloat16 g_hw2th[(size_t)OPAD * NNODE];
__device__ __align__(16) float g_g[(size_t)NNODE * OPAD];
__device__ float g_b2p[OPAD];
__device__ float g_dinv[NNODE];
__device__ int   g_deg[NNODE];
__device__ int   g_perm[NNODE];
__device__ int   g_iperm[NNODE];
__device__ int   g_c0;
__device__ double g_s0d[CDIM], g_s1d[CDIM];
__device__ unsigned long long g_cnt;
__device__ int   g_ncand;
__device__ int2  g_cand[CAND_CAP];

// ---------------- PTX helpers (all sm_80-compatible) ---------------------------
__device__ __forceinline__ uint32_t smem_u32(const void* p) {
    uint32_t a;
    asm("{ .reg .u64 t; cvta.to.shared.u64 t, %1; cvt.u32.u64 %0, t; }" : "=r"(a) : "l"(p));
    return a;
}
__device__ __forceinline__ void cp16(uint32_t d, const void* g) {
    asm volatile("cp.async.cg.shared.global [%0], [%1], 16;" :: "r"(d), "l"(g));
}
#define CP_COMMIT() asm volatile("cp.async.commit_group;" ::: "memory")
template<int N> __device__ __forceinline__ void cp_wait() {
    asm volatile("cp.async.wait_group %0;" :: "n"(N) : "memory");
}
__device__ __forceinline__ void ldm_x4(uint32_t* r, uint32_t addr) {
    asm volatile("ldmatrix.sync.aligned.m8n8.x4.shared.b16 {%0,%1,%2,%3}, [%4];"
        : "=r"(r[0]), "=r"(r[1]), "=r"(r[2]), "=r"(r[3]) : "r"(addr));
}
__device__ __forceinline__ void mma_bf16(float* c, const uint32_t* a, const uint32_t* b) {
    asm volatile(
        "mma.sync.aligned.m16n8k16.row.col.f32.bf16.bf16.f32 "
        "{%0,%1,%2,%3}, {%4,%5,%6,%7}, {%8,%9}, {%0,%1,%2,%3};"
        : "+f"(c[0]), "+f"(c[1]), "+f"(c[2]), "+f"(c[3])
        : "r"(a[0]), "r"(a[1]), "r"(a[2]), "r"(a[3]), "r"(b[0]), "r"(b[1]));
}
__device__ __forceinline__ void mma_fp16(float* c, const uint32_t* a, const uint32_t* b) {
    asm volatile(
        "mma.sync.aligned.m16n8k16.row.col.f32.f16.f16.f32 "
        "{%0,%1,%2,%3}, {%4,%5,%6,%7}, {%8,%9}, {%0,%1,%2,%3};"
        : "+f"(c[0]), "+f"(c[1]), "+f"(c[2]), "+f"(c[3])
        : "r"(a[0]), "r"(a[1]), "r"(a[2]), "r"(a[3]), "r"(b[0]), "r"(b[1]));
}

// Deterministic warp-collective threshold: identical code in every caller
// => bit-identical float result everywhere it is evaluated.
__device__ __forceinline__ float thr_warp() {
    double s = 0.0;
    const int lane = threadIdx.x & 31;
    for (int c = lane; c < CDIM; c += 32) s += g_s0d[c] * g_s1d[c];
#pragma unroll
    for (int o = 16; o > 0; o >>= 1) s += __shfl_xor_sync(0xFFFFFFFFu, s, o);
    unsigned long long cnt = g_cnt;
    return (cnt > 0ULL) ? (float)(2.0 * s / (double)cnt) : 0.f;
}

// ---------------- mma.sync GEMM: D[M,N] = A[M,K] * B[N,K]^T (single term) -----
// EPI_SIM: fused graph build (sorted space). Cross-label tiles just write zeros.
// EPI_H/EPI_G: K-range restricted to the row block's own label range.
template<int TN, bool FP16, int EPI>
__global__ void __launch_bounds__(256)
mma_gemm_k(const __nv_bfloat16* __restrict__ A0, const __nv_bfloat16* __restrict__ B0,
           int K, int lda, int ldb,
           float* __restrict__ fout, __nv_bfloat16* __restrict__ oh,
           const float* __restrict__ bias)
{
    constexpr int WN = 32;
    constexpr int WM = (TN == 128) ? 64 : 32;
    constexpr int WX = TN / WN;
    constexpr int MI = WM / 16;
    constexpr int NJ = WN / 8;
    constexpr int ASTG = 128 * 128;
    constexpr int BSTG = TN * 128;
    constexpr int STG = ASTG + BSTG;

    const int c0 = g_c0;
    const int tid = threadIdx.x;
    int bm, bn;
    bool diag = true;
    if (EPI == EPI_SIM) {
        int idx = blockIdx.x;
        int bi = 0;
        while (idx >= 32 - bi) { idx -= 32 - bi; bi++; }
        int bj = bi + idx;
        bm = bi * 128;
        bn = bj * 128;
        diag = (bi == bj);
        if (bm + 128 <= c0 && bn >= c0) {
            // fully cross-label: a01 is zero in both mirrored blocks
            const uint4 z4 = make_uint4(0u, 0u, 0u, 0u);
            for (int q = tid; q < 128 * 16; q += 256) {
                const int r = q >> 4, c16 = q & 15;
                *reinterpret_cast<uint4*>(g_a01 + (size_t)(bm + r) * NNODE + bn + c16 * 8) = z4;
                *reinterpret_cast<uint4*>(g_a01 + (size_t)(bn + r) * NNODE + bm + c16 * 8) = z4;
            }
            return;
        }
    } else {
        bm = blockIdx.y * 128;
        bn = blockIdx.x * TN;
    }

    extern __shared__ char smem[];
    __shared__ int s_degM[128];
    __shared__ int s_degN[128];
    __shared__ float s_thr;
    const uint32_t sb = smem_u32(smem);
    const int w = tid >> 5, lane = tid & 31;
    const int wm = (w / WX) * WM, wn = (w % WX) * WN;

    if (EPI == EPI_SIM && w == 0) {
        float t = thr_warp();
        if (lane == 0) s_thr = t;
    }

    float acc[MI][NJ][4];
#pragma unroll
    for (int i = 0; i < MI; i++)
#pragma unroll
        for (int j = 0; j < NJ; j++)
#pragma unroll
            for (int q = 0; q < 4; q++) acc[i][j][q] = 0.f;

    // K-chunk range (block-diagonal skip for aggregation GEMMs)
    int cl = 0, chi = K >> 6;
    if (EPI == EPI_H || EPI == EPI_G) {
        if (bm + 128 <= c0)   chi = min(chi, (c0 + 63) >> 6);
        else if (bm >= c0)    cl = c0 >> 6;
    }
    const int nch = chi - cl;

    auto load_stage = [&](int s, int kc) {
        const uint32_t sA = sb + s * STG;
        const uint32_t sB = sA + ASTG;
#pragma unroll
        for (int i = 0; i < 4; i++) {
            int q = i * 256 + tid;
            int r = q >> 3, c = q & 7;
            cp16(sA + r * 128 + (((c ^ (r & 7)) << 4)),
                 A0 + (size_t)(bm + r) * lda + kc * 64 + c * 8);
        }
#pragma unroll
        for (int i = 0; i < TN / 32; i++) {
            int q = i * 256 + tid;
            int r = q >> 3, c = q & 7;
            cp16(sB + r * 128 + (((c ^ (r & 7)) << 4)),
                 B0 + (size_t)(bn + r) * ldb + kc * 64 + c * 8);
        }
        CP_COMMIT();
    };

    load_stage(0, cl);
    for (int t = 0; t < nch; t++) {
        if (t + 1 < nch) {
            load_stage((t + 1) & 1, cl + t + 1);
            cp_wait<1>();
        } else {
            cp_wait<0>();
        }
        __syncthreads();

        const uint32_t sA = sb + (t & 1) * STG;
        const uint32_t sB = sA + ASTG;
#pragma unroll
        for (int kk = 0; kk < 4; kk++) {
            uint32_t a[MI][4];
#pragma unroll
            for (int i = 0; i < MI; i++) {
                int r = wm + i * 16 + (lane & 15);
                int c = kk * 2 + (lane >> 4);
                ldm_x4(a[i], sA + r * 128 + (((c ^ (r & 7)) << 4)));
            }
            uint32_t b[NJ][2];
#pragma unroll
            for (int jj = 0; jj < NJ / 2; jj++) {
                int mat = lane >> 3;
                int tile = 2 * jj + (mat >> 1);
                int kh = mat & 1;
                int n = wn + tile * 8 + (lane & 7);
                int c = kk * 2 + kh;
                uint32_t r4[4];
                ldm_x4(r4, sB + n * 128 + (((c ^ (n & 7)) << 4)));
                b[2 * jj][0] = r4[0]; b[2 * jj][1] = r4[1];
                b[2 * jj + 1][0] = r4[2]; b[2 * jj + 1][1] = r4[3];
            }
#pragma unroll
            for (int i = 0; i < MI; i++)
#pragma unroll
                for (int j = 0; j < NJ; j++) {
                    if (FP16) mma_fp16(acc[i][j], a[i], b[j]);
                    else      mma_bf16(acc[i][j], a[i], b[j]);
                }
        }
        __syncthreads();
    }
    // pipeline smem dead; EPI_SIM off-diag reuses it as 128x128 bf16 mirror tile
    __nv_bfloat16* sT = reinterpret_cast<__nv_bfloat16*>(smem);
    if (EPI == EPI_SIM) {
        if (tid < 128) { s_degM[tid] = 0; s_degN[tid] = 0; }
        __syncthreads();
    }

    // -------- epilogue -------------------------------------------------------
    const int g4 = lane >> 2, t4 = lane & 3;
    const float thr = (EPI == EPI_SIM) ? s_thr : 0.f;
#pragma unroll
    for (int i = 0; i < MI; i++) {
#pragma unroll
        for (int p = 0; p < 2; p++) {
            const int ml = wm + i * 16 + g4 + p * 8;
            const int m = bm + ml;
            float dl = 1.f;
            if (EPI != EPI_SIM) dl = g_dinv[m];
            const bool mlab = (EPI == EPI_SIM) && (m < c0);
#pragma unroll
            for (int j = 0; j < NJ; j++) {
                const int nl = wn + j * 8 + t4 * 2;   // even
                const int n = bn + nl;
                const float v0 = acc[i][j][2 * p + 0];
                const float v1 = acc[i][j][2 * p + 1];
                if (EPI == EPI_SIM) {
                    const bool same0 = ((n < c0) == mlab) && (m != n);
                    const bool same1 = ((n + 1 < c0) == mlab) && (m != n + 1);
                    const bool e0 = same0 && (v0 <= thr);
                    const bool e1 = same1 && (v1 <= thr);
                    const float a0 = (e0 || m == n) ? 1.f : 0.f;
                    const float a1 = (e1 || m == n + 1) ? 1.f : 0.f;
                    *reinterpret_cast<__nv_bfloat162*>(g_a01 + (size_t)m * NNODE + n) =
                        __floats2bfloat162_rn(a0, a1);
                    atomicAdd(&s_degM[ml], (e0 ? 1 : 0) + (e1 ? 1 : 0));
                    if (!diag) {
                        if (e0) atomicAdd(&s_degN[nl], 1);
                        if (e1) atomicAdd(&s_degN[nl + 1], 1);
                    }
                    if (same0 && m < n && fabsf(v0 - thr) < FIXWIN) {
                        int pos = atomicAdd(&g_ncand, 1);
                        if (pos < CAND_CAP)
                            g_cand[pos] = make_int2(m, n | (e0 ? (int)0x80000000 : 0));
                    }
                    if (same1 && m < n + 1 && fabsf(v1 - thr) < FIXWIN) {
                        int pos = atomicAdd(&g_ncand, 1);
                        if (pos < CAND_CAP)
                            g_cand[pos] = make_int2(m, (n + 1) | (e1 ? (int)0x80000000 : 0));
                    }
                    if (!diag) {
                        const int swz = ((nl >> 1) & 3) << 3;
                        sT[nl * 128 + (ml ^ swz)] = __float2bfloat16(a0);
                        sT[(nl + 1) * 128 + (ml ^ swz)] = __float2bfloat16(a1);
                    }
                } else if (EPI == EPI_XW1T || EPI == EPI_HW2T) {
                    oh[(size_t)n * NNODE + m] = __float2bfloat16(dl * v0);
                    oh[(size_t)(n + 1) * NNODE + m] = __float2bfloat16(dl * v1);
                } else if (EPI == EPI_H) {
                    float s0 = fmaxf(dl * v0 + bias[n], 0.f);
                    float s1 = fmaxf(dl * v1 + bias[n + 1], 0.f);
                    *reinterpret_cast<__nv_bfloat162*>(oh + (size_t)m * HDIM + n) =
                        __nv_bfloat162(__float2bfloat16(s0), __float2bfloat16(s1));
                } else { // EPI_G
                    *reinterpret_cast<float2*>(fout + (size_t)m * OPAD + n) =
                        make_float2(dl * v0 + bias[n], dl * v1 + bias[n + 1]);
                }
            }
        }
    }
    if (EPI == EPI_SIM) {
        __syncthreads();
        if (tid < 128) {
            atomicAdd(&g_deg[bm + tid], s_degM[tid]);
            if (!diag) atomicAdd(&g_deg[bn + tid], s_degN[tid]);
        }
        if (!diag) {
            for (int q = tid; q < 128 * 64; q += 256) {
                const int nl = q >> 6, mp = (q & 63) * 2;
                const int swz = ((nl >> 1) & 3) << 3;
                __nv_bfloat162 u;
                u.x = sT[nl * 128 + (mp ^ swz)];
                u.y = sT[nl * 128 + ((mp + 1) ^ swz)];
                *reinterpret_cast<__nv_bfloat162*>(
                    g_a01 + (size_t)(bn + nl) * NNODE + bm + mp) = u;
            }
        }
    }
}

// ---------------- labels: dtype detect + stable label-sort perm + inverse -----
__global__ void lab_k(const int* __restrict__ p) {
    __shared__ int so[256];
    __shared__ int sc[256];
    const int t = threadIdx.x;
    for (int i = t; i < CDIM; i += 256) { g_s0d[i] = 0.0; g_s1d[i] = 0.0; }
    for (int i = t; i < NNODE; i += 256) g_deg[i] = 0;
    int o = 0;
    for (int i = t; i < NNODE / 2; i += 256) o |= p[2 * i + 1];
    so[t] = o;
    __syncthreads();
    for (int off = 128; off > 0; off >>= 1) {
        if (t < off) so[t] |= so[t + off];
        __syncthreads();
    }
    const bool is32 = (so[0] != 0);
    const int base = t * 16;
    int lv[16];
    int z = 0;
    for (int k = 0; k < 16; k++) {
        int v = is32 ? p[base + k] : p[2 * (base + k)];
        lv[k] = v;
        z += (v == 0) ? 1 : 0;
    }
    sc[t] = z;
    __syncthreads();
    for (int off = 1; off < 256; off <<= 1) {   // inclusive Hillis-Steele scan
        int val = (t >= off) ? sc[t - off] : 0;
        __syncthreads();
        sc[t] += val;
        __syncthreads();
    }
    const int c0 = sc[255];
    int p0 = sc[t] - z;                 // zeros before my chunk
    int p1 = c0 + (base - (sc[t] - z)); // ones before my chunk
    for (int k = 0; k < 16; k++) {
        if (lv[k] == 0) { g_perm[p0] = base + k; g_iperm[base + k] = p0; p0++; }
        else            { g_perm[p1] = base + k; g_iperm[base + k] = p1; p1++; }
    }
    if (t == 0) {
        g_c0 = c0;
        unsigned long long cz = (unsigned long long)c0;
        g_cnt = 2ULL * cz * (unsigned long long)(NNODE - c0);
        g_ncand = 0;
    }
}

// ---------------- fused: permuted x converts + per-label column sums ----------
__global__ void split_x_k(const float* __restrict__ x) {
    const int b = blockIdx.x;           // 1024 blocks x 4 rows
    const int t = threadIdx.x;
    const int c0 = g_c0;
    float a0[3] = {0.f, 0.f, 0.f}, a1[3] = {0.f, 0.f, 0.f};
    for (int s = b * 4; s < b * 4 + 4; s++) {
        const int orig = g_perm[s];
        const float* row = x + (size_t)orig * CDIM;
        const bool l1 = (s >= c0);
#pragma unroll
        for (int q = 0; q < 3; q++) {
            const int col = t + q * 256;
            float v = row[col];
            g_xf16[(size_t)s * CDIM + col] = __float2half(v);
            g_xbh[(size_t)s * CDIM + col] = __float2bfloat16(v);
            if (l1) a1[q] += v; else a0[q] += v;
        }
    }
#pragma unroll
    for (int q = 0; q < 3; q++) {
        atomicAdd(&g_s0d[t + q * 256], (double)a0[q]);
        atomicAdd(&g_s1d[t + q * 256], (double)a1[q]);
    }
}

// ---------------- weights: transpose + bf16 + pad -----------------------------
__global__ void prep_w_k(const float* __restrict__ W1, const float* __restrict__ W2,
                         const float* __restrict__ b2) {
    size_t idx = (size_t)blockIdx.x * blockDim.x + threadIdx.x;
    size_t stride = (size_t)gridDim.x * blockDim.x;
    if (idx < OPAD) g_b2p[idx] = (idx < ODIM) ? b2[idx] : 0.f;
    size_t t1 = (size_t)HDIM * CDIM;
    for (size_t t = idx; t < t1; t += stride) {
        int n = (int)(t / CDIM), k = (int)(t % CDIM);
        g_w1th[t] = __float2bfloat16(W1[(size_t)k * HDIM + n]);
    }
    size_t t2 = (size_t)OPAD * HDIM;
    for (size_t t = idx; t < t2; t += stride) {
        int n = (int)(t / HDIM), k = (int)(t % HDIM);
        g_w2th[t] = __float2bfloat16((n < ODIM) ? W2[(size_t)k * ODIM + n] : 0.f);
    }
}

// ---------------- fixup: exact fp32 dot, warp per candidate; patch on flip ----
__global__ void fix_k(const float* __restrict__ x) {
    int nc = g_ncand;
    if (nc > CAND_CAP) nc = CAND_CAP;
    const float thr = thr_warp();
    const int gw = (blockIdx.x * blockDim.x + threadIdx.x) >> 5;
    const int lane = threadIdx.x & 31;
    const int nw = (gridDim.x * blockDim.x) >> 5;
    for (int cid = gw; cid < nc; cid += nw) {
        int2 c = g_cand[cid];
        const int i = c.x;                       // sorted
        const int j = c.y & 0x7FFFFFFF;          // sorted, i<j
        const bool prov = (c.y < 0);
        const int oi = g_perm[i], oj = g_perm[j];
        const float4* xi = reinterpret_cast<const float4*>(x + (size_t)oi * CDIM);
        const float4* xj = reinterpret_cast<const float4*>(x + (size_t)oj * CDIM);
        float s = 0.f;
        for (int k = lane; k < CDIM / 4; k += 32) {
            float4 a = xi[k], b = xj[k];
            s += a.x * b.x + a.y * b.y + a.z * b.z + a.w * b.w;
        }
#pragma unroll
        for (int o = 16; o > 0; o >>= 1) s += __shfl_xor_sync(0xFFFFFFFFu, s, o);
        if (lane == 0) {
            const bool e = (s <= thr);
            if (e != prov) {
                const float av = e ? 1.f : 0.f;
                const __nv_bfloat16 ab = __float2bfloat16(av);
                g_a01[(size_t)i * NNODE + j] = ab;
                g_a01[(size_t)j * NNODE + i] = ab;
                const int d = e ? 1 : -1;
                atomicAdd(&g_deg[i], d);
                atomicAdd(&g_deg[j], d);
            }
        }
    }
}

// ---------------- dinv from degrees -------------------------------------------
__global__ void dinv_k() {
    int i = blockIdx.x * blockDim.x + threadIdx.x;
    if (i < NNODE) g_dinv[i] = rsqrtf((float)(g_deg[i] + 1));
}

// ---------------- loss_mask: coalesced permuted rebuild from final a01 --------
// lm[i][j] = (j > i) && edge(sorted(i), sorted(j)); self-loop excluded by j>i.
__global__ void lmperm_k(float* __restrict__ lm) {
    __shared__ uint4 srow[512];         // 8KB: a01 row (sorted space)
    __shared__ uint32_t bits[128];      // 4096-bit edge mask
    const int i = blockIdx.x;           // original row
    const int tid = threadIdx.x;
    const int si = g_iperm[i];
    const uint4* arow = reinterpret_cast<const uint4*>(g_a01 + (size_t)si * NNODE);
    srow[tid] = arow[tid];
    srow[tid + 256] = arow[tid + 256];
    __syncthreads();
    if (tid < 128) {
        const uint16_t* r = reinterpret_cast<const uint16_t*>(srow);
        uint32_t wd = 0;
#pragma unroll
        for (int k = 0; k < 32; k++)
            if (r[tid * 32 + k] != 0) wd |= (1u << k);
        bits[tid] = wd;
    }
    __syncthreads();
    float* dst = lm + (size_t)i * NNODE;
    for (int j0 = tid * 4; j0 < NNODE; j0 += 1024) {
        float v[4];
#pragma unroll
        for (int q = 0; q < 4; q++) {
            const int j = j0 + q;
            const int t = g_iperm[j];
            v[q] = (j > i && ((bits[t >> 5] >> (t & 31)) & 1u)) ? 1.f : 0.f;
        }
        *reinterpret_cast<float4*>(dst + j0) = make_float4(v[0], v[1], v[2], v[3]);
    }
}

// ---------------- fused f_g + x copy + final GEMV (permuted writeback) --------
__global__ void fgout_k(const float* __restrict__ x, const float* __restrict__ fcW,
                        const float* __restrict__ fcb, float* __restrict__ out,
                        float* __restrict__ fg, float* __restrict__ xout, int full) {
    const int s = blockIdx.x;            // sorted node
    const int orig = g_perm[s];
    const int FDIM = CDIM + ODIM;
    const float* xr = x + (size_t)orig * CDIM;
    float acc = 0.f;
    for (int c = threadIdx.x; c < CDIM; c += 256) {
        float v = xr[c];
        acc += v * fcW[c];
        if (full) {
            fg[(size_t)orig * FDIM + c] = v;
            xout[(size_t)orig * CDIM + c] = v;
        }
    }
    for (int o = threadIdx.x; o < ODIM; o += 256) {
        float v = g_g[(size_t)s * OPAD + o];
        acc += v * fcW[CDIM + o];
        if (full) fg[(size_t)orig * FDIM + CDIM + o] = v;
    }
    __shared__ float sh[256];
    sh[threadIdx.x] = acc;
    __syncthreads();
    for (int off = 128; off > 0; off >>= 1) {
        if (threadIdx.x < off) sh[threadIdx.x] += sh[threadIdx.x + off];
        __syncthreads();
    }
    if (threadIdx.x == 0) out[orig] = sh[0] + fcb[0];
}

// ---------------- launch ------------------------------------------------------
extern "C" void kernel_launch(void* const* d_in, const int* in_sizes, int n_in,
                              void* d_out, int out_size) {
    const float* x   = (const float*)d_in[0];
    const int*   lab = (const int*)d_in[1];
    const float* W1  = (const float*)d_in[2];
    const float* b1  = (const float*)d_in[3];
    const float* W2  = (const float*)d_in[4];
    const float* b2  = (const float*)d_in[5];
    const float* fcW = (const float*)d_in[6];
    const float* fcb = (const float*)d_in[7];
    (void)in_sizes; (void)n_in;

    const size_t SZ_OUT = NNODE;
    const size_t SZ_FG  = (size_t)NNODE * (CDIM + ODIM);
    const size_t SZ_LM  = (size_t)NNODE * NNODE;
    const size_t SZ_X   = (size_t)NNODE * CDIM;
    const bool full = ((size_t)out_size >= SZ_OUT + SZ_FG + SZ_LM + SZ_X);

    float* o_out = (float*)d_out;
    float* o_fg  = o_out + SZ_OUT;
    float* o_lm  = o_fg + SZ_FG;
    float* o_x   = o_lm + SZ_LM;

    __nv_bfloat16 *xbh, *w1th, *w2th, *xw1th, *hh, *hw2th, *a01;
    __half* xf16;
    float *gp, *b2pp;
    cudaGetSymbolAddress((void**)&xf16, g_xf16);
    cudaGetSymbolAddress((void**)&xbh, g_xbh);
    cudaGetSymbolAddress((void**)&w1th, g_w1th);
    cudaGetSymbolAddress((void**)&w2th, g_w2th);
    cudaGetSymbolAddress((void**)&xw1th, g_xw1th);
    cudaGetSymbolAddress((void**)&hh, g_hh);
    cudaGetSymbolAddress((void**)&hw2th, g_hw2th);
    cudaGetSymbolAddress((void**)&a01, g_a01);
    cudaGetSymbolAddress((void**)&gp, g_g);
    cudaGetSymbolAddress((void**)&b2pp, g_b2p);

    const int SM128 = 2 * (128 * 128 + 128 * 128);  // 65536
    const int SM64  = 2 * (128 * 128 + 64 * 128);   // 49152
    cudaFuncSetAttribute(mma_gemm_k<128, true,  EPI_SIM>,  cudaFuncAttributeMaxDynamicSharedMemorySize, SM128);
    cudaFuncSetAttribute(mma_gemm_k<128, false, EPI_XW1T>, cudaFuncAttributeMaxDynamicSharedMemorySize, SM128);
    cudaFuncSetAttribute(mma_gemm_k<128, false, EPI_H>,    cudaFuncAttributeMaxDynamicSharedMemorySize, SM128);
    cudaFuncSetAttribute(mma_gemm_k<64, false, EPI_HW2T>,  cudaFuncAttributeMaxDynamicSharedMemorySize, SM64);
    cudaFuncSetAttribute(mma_gemm_k<64, false, EPI_G>,     cudaFuncAttributeMaxDynamicSharedMemorySize, SM64);

    // 0. labels + perm; permuted converts fused with label sums (thr inline later)
    lab_k<<<1, 256>>>(lab);
    split_x_k<<<1024, 256>>>(x);
    prep_w_k<<<256, 256>>>(W1, W2, b2);

    // 1. fused sim + graph build (fp16 MMA, sorted space; cross tiles write 0)
    mma_gemm_k<128, true, EPI_SIM><<<528, 256, SM128>>>(
        (const __nv_bfloat16*)xf16, (const __nv_bfloat16*)xf16,
        CDIM, CDIM, CDIM, nullptr, nullptr, nullptr);

    // 2. exact fp32 fixup + dinv
    fix_k<<<256, 256>>>(x);
    dinv_k<<<16, 256>>>();

    // 3. xw1 = x @ W1; write (dinv_j * xw1)^T bf16   [512 x 4096] (sorted)
    mma_gemm_k<128, false, EPI_XW1T><<<dim3(HDIM / 128, 32), 256, SM128>>>(
        xbh, w1th, CDIM, CDIM, CDIM, nullptr, xw1th, nullptr);

    // 4. h = relu(dinv_i * (a01 @ xw1t) + b1) bf16 [4096 x 512] (K block-diag)
    mma_gemm_k<128, false, EPI_H><<<dim3(HDIM / 128, 32), 256, SM128>>>(
        a01, xw1th, NNODE, NNODE, NNODE, nullptr, hh, b1);

    // 5. hw2 = h @ W2p; write (dinv_j * hw2)^T bf16  [64 x 4096]
    mma_gemm_k<64, false, EPI_HW2T><<<dim3(1, 32), 256, SM64>>>(
        hh, w2th, HDIM, HDIM, HDIM, nullptr, hw2th, nullptr);

    // 6. g = dinv_i * (a01 @ hw2t) + b2p [4096 x 64] fp32 (K block-diag)
    mma_gemm_k<64, false, EPI_G><<<dim3(1, 32), 256, SM64>>>(
        a01, hw2th, NNODE, NNODE, NNODE, gp, nullptr, b2pp);

    // 7. loss_mask rebuild (coalesced, original index space)
    if (full) lmperm_k<<<NNODE, 256>>>(o_lm);

    // 8. fused f_g + x copy + out GEMV (permuted writeback)
    fgout_k<<<NNODE, 256>>>(x, fcW, fcb, o_out, full ? o_fg : nullptr,
                            full ? o_x : nullptr, full ? 1 : 0);
}

// round 10
// speedup vs baseline: 1.0289x; 1.0289x over previous
#include <cuda_runtime.h>
#include <cuda_bf16.h>
#include <cuda_fp16.h>
#include <cstdint>

#define NNODE 4096
#define CDIM  768
#define HDIM  512
#define ODIM  50
#define OPAD  64

#define EPI_SIM  0
#define EPI_XW1T 1
#define EPI_H    2
#define EPI_HW2T 3
#define EPI_G    4

#define CAND_CAP 65536
#define FIXWIN 0.12f

// ---------------- device scratch (static: no allocations allowed) -------------
// Node-indexed arrays live in SORTED space (label-0 first, stable within label).
// g_perm: sorted -> original. g_iperm: original -> sorted.
__device__ __align__(16) __nv_bfloat16 g_a01[(size_t)NNODE * NNODE];
__device__ __align__(16) __half        g_xf16[(size_t)NNODE * CDIM];
__device__ __align__(16) __nv_bfloat16 g_xbh[(size_t)NNODE * CDIM];
__device__ __align__(16) __nv_bfloat16 g_w1th[(size_t)HDIM * CDIM];
__device__ __align__(16) __nv_bfloat16 g_w2th[(size_t)OPAD * HDIM];
__device__ __align__(16) __nv_bfloat16 g_xw1th[(size_t)HDIM * NNODE];
__device__ __align__(16) __nv_bfloat16 g_hh[(size_t)NNODE * HDIM];
__device__ __align__(16) __nv_bfloat16 g_hw2th[(size_t)OPAD * NNODE];
__device__ __align__(16) float g_g[(size_t)NNODE * OPAD];
__device__ float g_b2p[OPAD];
__device__ float g_dinv[NNODE];
__device__ int   g_deg[NNODE];
__device__ int   g_perm[NNODE];
__device__ int   g_iperm[NNODE];
__device__ int   g_c0;
__device__ double g_s0d[CDIM], g_s1d[CDIM];
__device__ unsigned long long g_cnt;
__device__ int   g_ncand;
__device__ int2  g_cand[CAND_CAP];

// ---------------- PTX helpers (all sm_80-compatible) ---------------------------
__device__ __forceinline__ uint32_t smem_u32(const void* p) {
    uint32_t a;
    asm("{ .reg .u64 t; cvta.to.shared.u64 t, %1; cvt.u32.u64 %0, t; }" : "=r"(a) : "l"(p));
    return a;
}
__device__ __forceinline__ void cp16(uint32_t d, const void* g) {
    asm volatile("cp.async.cg.shared.global [%0], [%1], 16;" :: "r"(d), "l"(g));
}
#define CP_COMMIT() asm volatile("cp.async.commit_group;" ::: "memory")
template<int N> __device__ __forceinline__ void cp_wait() {
    asm volatile("cp.async.wait_group %0;" :: "n"(N) : "memory");
}
__device__ __forceinline__ void ldm_x4(uint32_t* r, uint32_t addr) {
    asm volatile("ldmatrix.sync.aligned.m8n8.x4.shared.b16 {%0,%1,%2,%3}, [%4];"
        : "=r"(r[0]), "=r"(r[1]), "=r"(r[2]), "=r"(r[3]) : "r"(addr));
}
__device__ __forceinline__ void mma_bf16(float* c, const uint32_t* a, const uint32_t* b) {
    asm volatile(
        "mma.sync.aligned.m16n8k16.row.col.f32.bf16.bf16.f32 "
        "{%0,%1,%2,%3}, {%4,%5,%6,%7}, {%8,%9}, {%0,%1,%2,%3};"
        : "+f"(c[0]), "+f"(c[1]), "+f"(c[2]), "+f"(c[3])
        : "r"(a[0]), "r"(a[1]), "r"(a[2]), "r"(a[3]), "r"(b[0]), "r"(b[1]));
}
__device__ __forceinline__ void mma_fp16(float* c, const uint32_t* a, const uint32_t* b) {
    asm volatile(
        "mma.sync.aligned.m16n8k16.row.col.f32.f16.f16.f32 "
        "{%0,%1,%2,%3}, {%4,%5,%6,%7}, {%8,%9}, {%0,%1,%2,%3};"
        : "+f"(c[0]), "+f"(c[1]), "+f"(c[2]), "+f"(c[3])
        : "r"(a[0]), "r"(a[1]), "r"(a[2]), "r"(a[3]), "r"(b[0]), "r"(b[1]));
}

// Deterministic warp-collective threshold: identical code in every caller
// => bit-identical float result everywhere it is evaluated.
__device__ __forceinline__ float thr_warp() {
    double s = 0.0;
    const int lane = threadIdx.x & 31;
    for (int c = lane; c < CDIM; c += 32) s += g_s0d[c] * g_s1d[c];
#pragma unroll
    for (int o = 16; o > 0; o >>= 1) s += __shfl_xor_sync(0xFFFFFFFFu, s, o);
    unsigned long long cnt = g_cnt;
    return (cnt > 0ULL) ? (float)(2.0 * s / (double)cnt) : 0.f;
}

// ---------------- mma.sync GEMM: D[M,N] = A[M,K] * B[N,K]^T (single term) -----
// EPI_SIM: fused graph build (sorted space). Cross-label tiles just write zeros.
// EPI_H/EPI_G: K-range restricted to the row block's own label range.
// EPI_XW1T/EPI_HW2T: transposed output staged in smem, coalesced writeback.
template<int TN, bool FP16, int EPI>
__global__ void __launch_bounds__(256)
mma_gemm_k(const __nv_bfloat16* __restrict__ A0, const __nv_bfloat16* __restrict__ B0,
           int K, int lda, int ldb,
           float* __restrict__ fout, __nv_bfloat16* __restrict__ oh,
           const float* __restrict__ bias)
{
    constexpr int WN = 32;
    constexpr int WM = (TN == 128) ? 64 : 32;
    constexpr int WX = TN / WN;
    constexpr int MI = WM / 16;
    constexpr int NJ = WN / 8;
    constexpr int ASTG = 128 * 128;
    constexpr int BSTG = TN * 128;
    constexpr int STG = ASTG + BSTG;

    const int c0 = g_c0;
    const int tid = threadIdx.x;
    int bm, bn;
    bool diag = true;
    if (EPI == EPI_SIM) {
        int idx = blockIdx.x;
        int bi = 0;
        while (idx >= 32 - bi) { idx -= 32 - bi; bi++; }
        int bj = bi + idx;
        bm = bi * 128;
        bn = bj * 128;
        diag = (bi == bj);
        if (bm + 128 <= c0 && bn >= c0) {
            // fully cross-label: a01 is zero in both mirrored blocks
            const uint4 z4 = make_uint4(0u, 0u, 0u, 0u);
            for (int q = tid; q < 128 * 16; q += 256) {
                const int r = q >> 4, c16 = q & 15;
                *reinterpret_cast<uint4*>(g_a01 + (size_t)(bm + r) * NNODE + bn + c16 * 8) = z4;
                *reinterpret_cast<uint4*>(g_a01 + (size_t)(bn + r) * NNODE + bm + c16 * 8) = z4;
            }
            return;
        }
    } else {
        bm = blockIdx.y * 128;
        bn = blockIdx.x * TN;
    }

    extern __shared__ char smem[];
    __shared__ int s_degM[128];
    __shared__ int s_degN[128];
    __shared__ float s_thr;
    const uint32_t sb = smem_u32(smem);
    const int w = tid >> 5, lane = tid & 31;
    const int wm = (w / WX) * WM, wn = (w % WX) * WN;

    if (EPI == EPI_SIM && w == 0) {
        float t = thr_warp();
        if (lane == 0) s_thr = t;
    }

    float acc[MI][NJ][4];
#pragma unroll
    for (int i = 0; i < MI; i++)
#pragma unroll
        for (int j = 0; j < NJ; j++)
#pragma unroll
            for (int q = 0; q < 4; q++) acc[i][j][q] = 0.f;

    // K-chunk range (block-diagonal skip for aggregation GEMMs)
    int cl = 0, chi = K >> 6;
    if (EPI == EPI_H || EPI == EPI_G) {
        if (bm + 128 <= c0)   chi = min(chi, (c0 + 63) >> 6);
        else if (bm >= c0)    cl = c0 >> 6;
    }
    const int nch = chi - cl;

    auto load_stage = [&](int s, int kc) {
        const uint32_t sA = sb + s * STG;
        const uint32_t sB = sA + ASTG;
#pragma unroll
        for (int i = 0; i < 4; i++) {
            int q = i * 256 + tid;
            int r = q >> 3, c = q & 7;
            cp16(sA + r * 128 + (((c ^ (r & 7)) << 4)),
                 A0 + (size_t)(bm + r) * lda + kc * 64 + c * 8);
        }
#pragma unroll
        for (int i = 0; i < TN / 32; i++) {
            int q = i * 256 + tid;
            int r = q >> 3, c = q & 7;
            cp16(sB + r * 128 + (((c ^ (r & 7)) << 4)),
                 B0 + (size_t)(bn + r) * ldb + kc * 64 + c * 8);
        }
        CP_COMMIT();
    };

    load_stage(0, cl);
    for (int t = 0; t < nch; t++) {
        if (t + 1 < nch) {
            load_stage((t + 1) & 1, cl + t + 1);
            cp_wait<1>();
        } else {
            cp_wait<0>();
        }
        __syncthreads();

        const uint32_t sA = sb + (t & 1) * STG;
        const uint32_t sB = sA + ASTG;
#pragma unroll
        for (int kk = 0; kk < 4; kk++) {
            uint32_t a[MI][4];
#pragma unroll
            for (int i = 0; i < MI; i++) {
                int r = wm + i * 16 + (lane & 15);
                int c = kk * 2 + (lane >> 4);
                ldm_x4(a[i], sA + r * 128 + (((c ^ (r & 7)) << 4)));
            }
            uint32_t b[NJ][2];
#pragma unroll
            for (int jj = 0; jj < NJ / 2; jj++) {
                int mat = lane >> 3;
                int tile = 2 * jj + (mat >> 1);
                int kh = mat & 1;
                int n = wn + tile * 8 + (lane & 7);
                int c = kk * 2 + kh;
                uint32_t r4[4];
                ldm_x4(r4, sB + n * 128 + (((c ^ (n & 7)) << 4)));
                b[2 * jj][0] = r4[0]; b[2 * jj][1] = r4[1];
                b[2 * jj + 1][0] = r4[2]; b[2 * jj + 1][1] = r4[3];
            }
#pragma unroll
            for (int i = 0; i < MI; i++)
#pragma unroll
                for (int j = 0; j < NJ; j++) {
                    if (FP16) mma_fp16(acc[i][j], a[i], b[j]);
                    else      mma_bf16(acc[i][j], a[i], b[j]);
                }
        }
        __syncthreads();
    }
    // pipeline smem dead; reuse as bf16 staging tile ([TN][128] or mirror)
    __nv_bfloat16* sT = reinterpret_cast<__nv_bfloat16*>(smem);
    if (EPI == EPI_SIM) {
        if (tid < 128) { s_degM[tid] = 0; s_degN[tid] = 0; }
        __syncthreads();
    }

    // -------- epilogue -------------------------------------------------------
    const int g4 = lane >> 2, t4 = lane & 3;
    const float thr = (EPI == EPI_SIM) ? s_thr : 0.f;
#pragma unroll
    for (int i = 0; i < MI; i++) {
#pragma unroll
        for (int p = 0; p < 2; p++) {
            const int ml = wm + i * 16 + g4 + p * 8;
            const int m = bm + ml;
            float dl = 1.f;
            if (EPI != EPI_SIM) dl = g_dinv[m];
            const bool mlab = (EPI == EPI_SIM) && (m < c0);
            int dcnt = 0;
#pragma unroll
            for (int j = 0; j < NJ; j++) {
                const int nl = wn + j * 8 + t4 * 2;   // even
                const int n = bn + nl;
                const float v0 = acc[i][j][2 * p + 0];
                const float v1 = acc[i][j][2 * p + 1];
                if (EPI == EPI_SIM) {
                    const bool same0 = ((n < c0) == mlab) && (m != n);
                    const bool same1 = ((n + 1 < c0) == mlab) && (m != n + 1);
                    const bool e0 = same0 && (v0 <= thr);
                    const bool e1 = same1 && (v1 <= thr);
                    const float a0 = (e0 || m == n) ? 1.f : 0.f;
                    const float a1 = (e1 || m == n + 1) ? 1.f : 0.f;
                    *reinterpret_cast<__nv_bfloat162*>(g_a01 + (size_t)m * NNODE + n) =
                        __floats2bfloat162_rn(a0, a1);
                    dcnt += (e0 ? 1 : 0) + (e1 ? 1 : 0);
                    if (!diag) {
                        if (e0) atomicAdd(&s_degN[nl], 1);
                        if (e1) atomicAdd(&s_degN[nl + 1], 1);
                    }
                    if (same0 && m < n && fabsf(v0 - thr) < FIXWIN) {
                        int pos = atomicAdd(&g_ncand, 1);
                        if (pos < CAND_CAP)
                            g_cand[pos] = make_int2(m, n | (e0 ? (int)0x80000000 : 0));
                    }
                    if (same1 && m < n + 1 && fabsf(v1 - thr) < FIXWIN) {
                        int pos = atomicAdd(&g_ncand, 1);
                        if (pos < CAND_CAP)
                            g_cand[pos] = make_int2(m, (n + 1) | (e1 ? (int)0x80000000 : 0));
                    }
                    if (!diag) {
                        const int swz = ((nl >> 1) & 3) << 3;
                        sT[nl * 128 + (ml ^ swz)] = __float2bfloat16(a0);
                        sT[(nl + 1) * 128 + (ml ^ swz)] = __float2bfloat16(a1);
                    }
                } else if (EPI == EPI_XW1T || EPI == EPI_HW2T) {
                    // stage transposed tile: sT[n_local][m_local]
                    sT[nl * 128 + ml] = __float2bfloat16(dl * v0);
                    sT[(nl + 1) * 128 + ml] = __float2bfloat16(dl * v1);
                } else if (EPI == EPI_H) {
                    float s0 = fmaxf(dl * v0 + bias[n], 0.f);
                    float s1 = fmaxf(dl * v1 + bias[n + 1], 0.f);
                    *reinterpret_cast<__nv_bfloat162*>(oh + (size_t)m * HDIM + n) =
                        __nv_bfloat162(__float2bfloat16(s0), __float2bfloat16(s1));
                } else { // EPI_G
                    *reinterpret_cast<float2*>(fout + (size_t)m * OPAD + n) =
                        make_float2(dl * v0 + bias[n], dl * v1 + bias[n + 1]);
                }
            }
            if (EPI == EPI_SIM) atomicAdd(&s_degM[ml], dcnt);
        }
    }
    if (EPI == EPI_XW1T || EPI == EPI_HW2T) {
        // coalesced transposed writeback: row n gets 128 contiguous m (256B)
        __syncthreads();
        for (int q = tid; q < TN * 16; q += 256) {
            const int row = q >> 4, c16 = q & 15;
            uint4 v = *reinterpret_cast<const uint4*>(sT + row * 128 + c16 * 8);
            *reinterpret_cast<uint4*>(oh + (size_t)(bn + row) * NNODE + bm + c16 * 8) = v;
        }
    }
    if (EPI == EPI_SIM) {
        __syncthreads();
        if (tid < 128) {
            atomicAdd(&g_deg[bm + tid], s_degM[tid]);
            if (!diag) atomicAdd(&g_deg[bn + tid], s_degN[tid]);
        }
        if (!diag) {
            for (int q = tid; q < 128 * 64; q += 256) {
                const int nl = q >> 6, mp = (q & 63) * 2;
                const int swz = ((nl >> 1) & 3) << 3;
                __nv_bfloat162 u;
                u.x = sT[nl * 128 + (mp ^ swz)];
                u.y = sT[nl * 128 + ((mp + 1) ^ swz)];
                *reinterpret_cast<__nv_bfloat162*>(
                    g_a01 + (size_t)(bn + nl) * NNODE + bm + mp) = u;
            }
        }
    }
}

// ---------------- labels: dtype detect + stable label-sort perm + inverse -----
__global__ void lab_k(const int* __restrict__ p) {
    __shared__ int so[256];
    __shared__ int sc[256];
    const int t = threadIdx.x;
    for (int i = t; i < CDIM; i += 256) { g_s0d[i] = 0.0; g_s1d[i] = 0.0; }
    for (int i = t; i < NNODE; i += 256) g_deg[i] = 0;
    int o = 0;
    for (int i = t; i < NNODE / 2; i += 256) o |= p[2 * i + 1];
    so[t] = o;
    __syncthreads();
    for (int off = 128; off > 0; off >>= 1) {
        if (t < off) so[t] |= so[t + off];
        __syncthreads();
    }
    const bool is32 = (so[0] != 0);
    const int base = t * 16;
    int lv[16];
    int z = 0;
    for (int k = 0; k < 16; k++) {
        int v = is32 ? p[base + k] : p[2 * (base + k)];
        lv[k] = v;
        z += (v == 0) ? 1 : 0;
    }
    sc[t] = z;
    __syncthreads();
    for (int off = 1; off < 256; off <<= 1) {   // inclusive Hillis-Steele scan
        int val = (t >= off) ? sc[t - off] : 0;
        __syncthreads();
        sc[t] += val;
        __syncthreads();
    }
    const int c0 = sc[255];
    int p0 = sc[t] - z;                 // zeros before my chunk
    int p1 = c0 + (base - (sc[t] - z)); // ones before my chunk
    for (int k = 0; k < 16; k++) {
        if (lv[k] == 0) { g_perm[p0] = base + k; g_iperm[base + k] = p0; p0++; }
        else            { g_perm[p1] = base + k; g_iperm[base + k] = p1; p1++; }
    }
    if (t == 0) {
        g_c0 = c0;
        unsigned long long cz = (unsigned long long)c0;
        g_cnt = 2ULL * cz * (unsigned long long)(NNODE - c0);
        g_ncand = 0;
    }
}

// ---------------- fused: permuted x converts + per-label column sums ----------
__global__ void split_x_k(const float* __restrict__ x) {
    const int b = blockIdx.x;           // 1024 blocks x 4 rows
    const int t = threadIdx.x;
    const int c0 = g_c0;
    float a0[3] = {0.f, 0.f, 0.f}, a1[3] = {0.f, 0.f, 0.f};
    for (int s = b * 4; s < b * 4 + 4; s++) {
        const int orig = g_perm[s];
        const float* row = x + (size_t)orig * CDIM;
        const bool l1 = (s >= c0);
#pragma unroll
        for (int q = 0; q < 3; q++) {
            const int col = t + q * 256;
            float v = row[col];
            g_xf16[(size_t)s * CDIM + col] = __float2half(v);
            g_xbh[(size_t)s * CDIM + col] = __float2bfloat16(v);
            if (l1) a1[q] += v; else a0[q] += v;
        }
    }
#pragma unroll
    for (int q = 0; q < 3; q++) {
        atomicAdd(&g_s0d[t + q * 256], (double)a0[q]);
        atomicAdd(&g_s1d[t + q * 256], (double)a1[q]);
    }
}

// ---------------- weights: transpose + bf16 + pad -----------------------------
__global__ void prep_w_k(const float* __restrict__ W1, const float* __restrict__ W2,
                         const float* __restrict__ b2) {
    size_t idx = (size_t)blockIdx.x * blockDim.x + threadIdx.x;
    size_t stride = (size_t)gridDim.x * blockDim.x;
    if (idx < OPAD) g_b2p[idx] = (idx < ODIM) ? b2[idx] : 0.f;
    size_t t1 = (size_t)HDIM * CDIM;
    for (size_t t = idx; t < t1; t += stride) {
        int n = (int)(t / CDIM), k = (int)(t % CDIM);
        g_w1th[t] = __float2bfloat16(W1[(size_t)k * HDIM + n]);
    }
    size_t t2 = (size_t)OPAD * HDIM;
    for (size_t t = idx; t < t2; t += stride) {
        int n = (int)(t / HDIM), k = (int)(t % HDIM);
        g_w2th[t] = __float2bfloat16((n < ODIM) ? W2[(size_t)k * ODIM + n] : 0.f);
    }
}

// ---------------- fixup: exact fp32 dot, warp per candidate; patch on flip ----
__global__ void fix_k(const float* __restrict__ x) {
    int nc = g_ncand;
    if (nc > CAND_CAP) nc = CAND_CAP;
    const float thr = thr_warp();
    const int gw = (blockIdx.x * blockDim.x + threadIdx.x) >> 5;
    const int lane = threadIdx.x & 31;
    const int nw = (gridDim.x * blockDim.x) >> 5;
    for (int cid = gw; cid < nc; cid += nw) {
        int2 c = g_cand[cid];
        const int i = c.x;                       // sorted
        const int j = c.y & 0x7FFFFFFF;          // sorted, i<j
        const bool prov = (c.y < 0);
        const int oi = g_perm[i], oj = g_perm[j];
        const float4* xi = reinterpret_cast<const float4*>(x + (size_t)oi * CDIM);
        const float4* xj = reinterpret_cast<const float4*>(x + (size_t)oj * CDIM);
        float s = 0.f;
        for (int k = lane; k < CDIM / 4; k += 32) {
            float4 a = xi[k], b = xj[k];
            s += a.x * b.x + a.y * b.y + a.z * b.z + a.w * b.w;
        }
#pragma unroll
        for (int o = 16; o > 0; o >>= 1) s += __shfl_xor_sync(0xFFFFFFFFu, s, o);
        if (lane == 0) {
            const bool e = (s <= thr);
            if (e != prov) {
                const float av = e ? 1.f : 0.f;
                const __nv_bfloat16 ab = __float2bfloat16(av);
                g_a01[(size_t)i * NNODE + j] = ab;
                g_a01[(size_t)j * NNODE + i] = ab;
                const int d = e ? 1 : -1;
                atomicAdd(&g_deg[i], d);
                atomicAdd(&g_deg[j], d);
            }
        }
    }
}

// ---------------- dinv from degrees -------------------------------------------
__global__ void dinv_k() {
    int i = blockIdx.x * blockDim.x + threadIdx.x;
    if (i < NNODE) g_dinv[i] = rsqrtf((float)(g_deg[i] + 1));
}

// ---------------- loss_mask: coalesced permuted rebuild from final a01 --------
// lm[i][j] = (j > i) && edge(sorted(i), sorted(j)); self-loop excluded by j>i.
__global__ void lmperm_k(float* __restrict__ lm) {
    __shared__ uint4 srow[512];         // 8KB: a01 row (sorted space)
    __shared__ uint32_t bits[128];      // 4096-bit edge mask
    const int i = blockIdx.x;           // original row
    const int tid = threadIdx.x;
    const int si = g_iperm[i];
    const uint4* arow = reinterpret_cast<const uint4*>(g_a01 + (size_t)si * NNODE);
    srow[tid] = arow[tid];
    srow[tid + 256] = arow[tid + 256];
    __syncthreads();
    if (tid < 128) {
        const uint16_t* r = reinterpret_cast<const uint16_t*>(srow);
        uint32_t wd = 0;
#pragma unroll
        for (int k = 0; k < 32; k++)
            if (r[tid * 32 + k] != 0) wd |= (1u << k);
        bits[tid] = wd;
    }
    __syncthreads();
    float* dst = lm + (size_t)i * NNODE;
    for (int j0 = tid * 4; j0 < NNODE; j0 += 1024) {
        float v[4];
#pragma unroll
        for (int q = 0; q < 4; q++) {
            const int j = j0 + q;
            const int t = g_iperm[j];
            v[q] = (j > i && ((bits[t >> 5] >> (t & 31)) & 1u)) ? 1.f : 0.f;
        }
        *reinterpret_cast<float4*>(dst + j0) = make_float4(v[0], v[1], v[2], v[3]);
    }
}

// ---------------- fused f_g + x copy + final GEMV (permuted writeback) --------
__global__ void fgout_k(const float* __restrict__ x, const float* __restrict__ fcW,
                        const float* __restrict__ fcb, float* __restrict__ out,
                        float* __restrict__ fg, float* __restrict__ xout, int full) {
    const int s = blockIdx.x;            // sorted node
    const int orig = g_perm[s];
    const int FDIM = CDIM + ODIM;
    const float* xr = x + (size_t)orig * CDIM;
    float acc = 0.f;
    for (int c = threadIdx.x; c < CDIM; c += 256) {
        float v = xr[c];
        acc += v * fcW[c];
        if (full) {
            fg[(size_t)orig * FDIM + c] = v;
            xout[(size_t)orig * CDIM + c] = v;
        }
    }
    for (int o = threadIdx.x; o < ODIM; o += 256) {
        float v = g_g[(size_t)s * OPAD + o];
        acc += v * fcW[CDIM + o];
        if (full) fg[(size_t)orig * FDIM + CDIM + o] = v;
    }
    __shared__ float sh[256];
    sh[threadIdx.x] = acc;
    __syncthreads();
    for (int off = 128; off > 0; off >>= 1) {
        if (threadIdx.x < off) sh[threadIdx.x] += sh[threadIdx.x + off];
        __syncthreads();
    }
    if (threadIdx.x == 0) out[orig] = sh[0] + fcb[0];
}

// ---------------- launch ------------------------------------------------------
extern "C" void kernel_launch(void* const* d_in, const int* in_sizes, int n_in,
                              void* d_out, int out_size) {
    const float* x   = (const float*)d_in[0];
    const int*   lab = (const int*)d_in[1];
    const float* W1  = (const float*)d_in[2];
    const float* b1  = (const float*)d_in[3];
    const float* W2  = (const float*)d_in[4];
    const float* b2  = (const float*)d_in[5];
    const float* fcW = (const float*)d_in[6];
    const float* fcb = (const float*)d_in[7];
    (void)in_sizes; (void)n_in;

    const size_t SZ_OUT = NNODE;
    const size_t SZ_FG  = (size_t)NNODE * (CDIM + ODIM);
    const size_t SZ_LM  = (size_t)NNODE * NNODE;
    const size_t SZ_X   = (size_t)NNODE * CDIM;
    const bool full = ((size_t)out_size >= SZ_OUT + SZ_FG + SZ_LM + SZ_X);

    float* o_out = (float*)d_out;
    float* o_fg  = o_out + SZ_OUT;
    float* o_lm  = o_fg + SZ_FG;
    float* o_x   = o_lm + SZ_LM;

    __nv_bfloat16 *xbh, *w1th, *w2th, *xw1th, *hh, *hw2th, *a01;
    __half* xf16;
    float *gp, *b2pp;
    cudaGetSymbolAddress((void**)&xf16, g_xf16);
    cudaGetSymbolAddress((void**)&xbh, g_xbh);
    cudaGetSymbolAddress((void**)&w1th, g_w1th);
    cudaGetSymbolAddress((void**)&w2th, g_w2th);
    cudaGetSymbolAddress((void**)&xw1th, g_xw1th);
    cudaGetSymbolAddress((void**)&hh, g_hh);
    cudaGetSymbolAddress((void**)&hw2th, g_hw2th);
    cudaGetSymbolAddress((void**)&a01, g_a01);
    cudaGetSymbolAddress((void**)&gp, g_g);
    cudaGetSymbolAddress((void**)&b2pp, g_b2p);

    const int SM128 = 2 * (128 * 128 + 128 * 128);  // 65536
    const int SM64  = 2 * (128 * 128 + 64 * 128);   // 49152
    cudaFuncSetAttribute(mma_gemm_k<128, true,  EPI_SIM>,  cudaFuncAttributeMaxDynamicSharedMemorySize, SM128);
    cudaFuncSetAttribute(mma_gemm_k<64, false, EPI_XW1T>,  cudaFuncAttributeMaxDynamicSharedMemorySize, SM64);
    cudaFuncSetAttribute(mma_gemm_k<64, false, EPI_H>,     cudaFuncAttributeMaxDynamicSharedMemorySize, SM64);
    cudaFuncSetAttribute(mma_gemm_k<64, false, EPI_HW2T>,  cudaFuncAttributeMaxDynamicSharedMemorySize, SM64);
    cudaFuncSetAttribute(mma_gemm_k<64, false, EPI_G>,     cudaFuncAttributeMaxDynamicSharedMemorySize, SM64);

    // 0. labels + perm; permuted converts fused with label sums (thr inline)
    lab_k<<<1, 256>>>(lab);
    split_x_k<<<1024, 256>>>(x);
    prep_w_k<<<256, 256>>>(W1, W2, b2);

    // 1. fused sim + graph build (fp16 MMA, sorted space; cross tiles write 0)
    mma_gemm_k<128, true, EPI_SIM><<<528, 256, SM128>>>(
        (const __nv_bfloat16*)xf16, (const __nv_bfloat16*)xf16,
        CDIM, CDIM, CDIM, nullptr, nullptr, nullptr);

    // 2. exact fp32 fixup + dinv
    fix_k<<<256, 256>>>(x);
    dinv_k<<<16, 256>>>();

    // 3. xw1 = x @ W1; write (dinv_j * xw1)^T bf16 [512 x 4096] (TN=64, staged)
    mma_gemm_k<64, false, EPI_XW1T><<<dim3(HDIM / 64, 32), 256, SM64>>>(
        xbh, w1th, CDIM, CDIM, CDIM, nullptr, xw1th, nullptr);

    // 4. h = relu(dinv_i * (a01 @ xw1t) + b1) bf16 [4096 x 512] (TN=64, K bd)
    mma_gemm_k<64, false, EPI_H><<<dim3(HDIM / 64, 32), 256, SM64>>>(
        a01, xw1th, NNODE, NNODE, NNODE, nullptr, hh, b1);

    // 5. hw2 = h @ W2p; write (dinv_j * hw2)^T bf16 [64 x 4096] (staged)
    mma_gemm_k<64, false, EPI_HW2T><<<dim3(1, 32), 256, SM64>>>(
        hh, w2th, HDIM, HDIM, HDIM, nullptr, hw2th, nullptr);

    // 6. g = dinv_i * (a01 @ hw2t) + b2p [4096 x 64] fp32 (K block-diag)
    mma_gemm_k<64, false, EPI_G><<<dim3(1, 32), 256, SM64>>>(
        a01, hw2th, NNODE, NNODE, NNODE, gp, nullptr, b2pp);

    // 7. loss_mask rebuild (coalesced, original index space)
    if (full) lmperm_k<<<NNODE, 256>>>(o_lm);

    // 8. fused f_g + x copy + out GEMV (permuted writeback)
    fgout_k<<<NNODE, 256>>>(x, fcW, fcb, o_out, full ? o_fg : nullptr,
                            full ? o_x : nullptr, full ? 1 : 0);
}